// round 3
// baseline (speedup 1.0000x reference)
#include <cuda_runtime.h>
#include <cstdint>

#define BATCH 8
#define HGT   1024
#define WID   1024
#define TY    4                    // output rows per warp strip
#define RAD   5                    // window radius (11x11)
#define NROWS (TY + 2 * RAD)       // 14 loaded rows per strip
#define NBLK  256                  // 256 blocks * 8 warps = 2048 strips = BATCH*HGT/TY
#define NPIX  (8.0 * 1024.0 * 1024.0)

__device__ float g_part[NBLK];

__global__ __launch_bounds__(256)
void edge_loss_kernel(const float* __restrict__ x, const int* __restrict__ tgt)
{
    const int lane = threadIdx.x & 31;
    const int warp = threadIdx.x >> 5;
    const int strip = blockIdx.x * 8 + warp;        // 0..2047
    const int b  = strip >> 8;                      // 256 strips per image
    const int y0 = (strip & 255) * TY;

    unsigned hor[NROWS], hand[NROWS], tw[NROWS];

    const int* tbase = tgt + (size_t)b * HGT * WID;

    // ---- Phase A: load target rows, pack bits, horizontal OR/AND over +-5 ----
    #pragma unroll
    for (int i = 0; i < NROWS; i++) {
        int row = y0 - RAD + i;
        unsigned w = 0u;
        if (row >= 0 && row < HGT) {
            const uint4* p = (const uint4*)(tbase + (size_t)row * WID + lane * 32);
            #pragma unroll
            for (int q = 0; q < 8; q++) {
                uint4 u = p[q];                      // target values are exactly 0 or 1
                unsigned nib = u.x | (u.y << 1) | (u.z << 2) | (u.w << 3);
                w |= nib << (4 * q);
            }
        }
        tw[i] = w;
        unsigned wl = __shfl_up_sync(0xffffffffu, w, 1);
        unsigned wr = __shfl_down_sync(0xffffffffu, w, 1);
        if (lane == 0)  wl = 0u;                     // zero padding at image left
        if (lane == 31) wr = 0u;                     // zero padding at image right
        unsigned o = w, a = w;
        #pragma unroll
        for (int s = 1; s <= RAD; s++) {
            unsigned r = __funnelshift_r(w, wr, s);  // column c+s
            unsigned l = __funnelshift_l(wl, w, s);  // column c-s
            o |= r | l;
            a &= r & l;
        }
        hor[i] = o;
        hand[i] = a;
    }

    // ---- Phase B: vertical OR/AND + fused log-softmax loss ----
    float acc = 0.0f;
    const float* xbase = x + (size_t)b * 2 * HGT * WID;

    #pragma unroll
    for (int t = 0; t < TY; t++) {
        unsigned vo = hor[t], va = hand[t];
        #pragma unroll
        for (int d = 1; d <= 2 * RAD; d++) { vo |= hor[t + d]; va &= hand[t + d]; }
        unsigned ew = vo ^ va;                       // edge bit: window not uniform
        unsigned tc = tw[t + RAD];                   // center-row target bits

        const int y = y0 + t;
        const float4* x0r = (const float4*)(xbase + (size_t)y * WID);
        const float4* x1r = (const float4*)(xbase + (size_t)(HGT + y) * WID);

        #pragma unroll
        for (int k = 0; k < 8; k++) {
            // lane processes cols [4*lane + 128*k, +4): coalesced 512B float4 loads
            int src = 4 * k + (lane >> 3);           // lane holding the bit word
            unsigned ewk = __shfl_sync(0xffffffffu, ew, src);
            unsigned twk = __shfl_sync(0xffffffffu, tc, src);
            int bitbase = (lane & 7) * 4;
            int idx4 = lane + 32 * k;
            float4 a0 = x0r[idx4];
            float4 a1 = x1r[idx4];
            #pragma unroll
            for (int j = 0; j < 4; j++) {
                float v0 = (&a0.x)[j];
                float v1 = (&a1.x)[j];
                unsigned tb = (twk >> (bitbase + j)) & 1u;
                unsigned eb = (ewk >> (bitbase + j)) & 1u;
                float xt = tb ? v1 : v0;
                float xo = tb ? v0 : v1;
                float mx = fmaxf(v0, v1);
                float lse = mx + __logf(1.0f + __expf(-fabsf(v0 - v1)));
                float c_off = xt - lse;
                float c_on  = 0.95f * xt + 0.1f * xo - 1.05f * lse;
                acc += eb ? c_on : c_off;
            }
        }
    }

    // ---- block reduction -> per-block partial ----
    #pragma unroll
    for (int o = 16; o > 0; o >>= 1)
        acc += __shfl_xor_sync(0xffffffffu, acc, o);

    __shared__ float ws[8];
    if (lane == 0) ws[warp] = acc;
    __syncthreads();
    if (threadIdx.x == 0) {
        float s = 0.0f;
        #pragma unroll
        for (int i = 0; i < 8; i++) s += ws[i];
        g_part[blockIdx.x] = s;
    }
}

__global__ __launch_bounds__(NBLK)
void finalize_kernel(float* __restrict__ out)
{
    const int tid = threadIdx.x;
    double v = (double)g_part[tid];
    #pragma unroll
    for (int o = 16; o > 0; o >>= 1)
        v += __shfl_xor_sync(0xffffffffu, v, o);

    __shared__ double ws[8];
    if ((tid & 31) == 0) ws[tid >> 5] = v;
    __syncthreads();
    if (tid == 0) {
        double s = 0.0;
        #pragma unroll
        for (int i = 0; i < 8; i++) s += ws[i];
        out[0] = (float)(-s / NPIX);
    }
}

extern "C" void kernel_launch(void* const* d_in, const int* in_sizes, int n_in,
                              void* d_out, int out_size)
{
    (void)in_sizes; (void)n_in; (void)out_size;
    const float* x   = (const float*)d_in[0];   // [8,2,1024,1024] float32
    const int*   tgt = (const int*)d_in[1];     // [8,1,1024,1024] int32

    edge_loss_kernel<<<NBLK, 256>>>(x, tgt);
    finalize_kernel<<<1, NBLK>>>((float*)d_out);
}

// round 8
// speedup vs baseline: 1.3409x; 1.3409x over previous
#include <cuda_runtime.h>
#include <cstdint>

#define HGT   1024
#define WID   1024
#define TY    8                      // output rows per block
#define RAD   5                      // 11x11 window radius
#define NROWS (TY + 2 * RAD)         // 18 halo rows per block
#define NBLK  1024                   // 8 images * 128 slabs
#define NPIX  (8.0 * 1024.0 * 1024.0)

__device__ float    g_part[NBLK];
__device__ unsigned g_done = 0;

__global__ __launch_bounds__(256)
void edge_loss_kernel(const float* __restrict__ x, const int* __restrict__ tgt,
                      float* __restrict__ out)
{
    const int lane = threadIdx.x & 31;
    const int warp = threadIdx.x >> 5;
    const int b    = blockIdx.x >> 7;            // image
    const int y0   = (blockIdx.x & 127) * TY;    // first output row of slab

    __shared__ unsigned s_hor [NROWS][32];
    __shared__ unsigned s_hand[NROWS][32];
    __shared__ unsigned s_tw  [NROWS][32];

    const int* tbase = tgt + (size_t)b * HGT * WID;

    // ---- Phase A (cooperative): pack 18 halo rows, horizontal OR/AND +-5 ----
    #pragma unroll
    for (int i = warp; i < NROWS; i += 8) {
        int row = y0 - RAD + i;
        unsigned w = 0u;
        if (row >= 0 && row < HGT) {
            const uint4* p = (const uint4*)(tbase + (size_t)row * WID + lane * 32);
            #pragma unroll
            for (int q = 0; q < 8; q++) {
                uint4 u = p[q];                  // target values are 0 or 1
                unsigned nib = u.x | (u.y << 1) | (u.z << 2) | (u.w << 3);
                w |= nib << (4 * q);
            }
        }
        unsigned wl = __shfl_up_sync(0xffffffffu, w, 1);
        unsigned wr = __shfl_down_sync(0xffffffffu, w, 1);
        if (lane == 0)  wl = 0u;                 // zero padding left
        if (lane == 31) wr = 0u;                 // zero padding right
        unsigned o = w, a = w;
        #pragma unroll
        for (int s = 1; s <= RAD; s++) {
            unsigned r = __funnelshift_r(w, wr, s);
            unsigned l = __funnelshift_l(wl, w, s);
            o |= r | l;
            a &= r & l;
        }
        s_tw[i][lane]   = w;
        s_hor[i][lane]  = o;
        s_hand[i][lane] = a;
    }
    __syncthreads();

    // ---- Phase B: one output row per warp; vertical combine from smem ----
    unsigned vo = 0u, va = 0xffffffffu;
    #pragma unroll
    for (int d = 0; d <= 2 * RAD; d++) {
        vo |= s_hor [warp + d][lane];
        va &= s_hand[warp + d][lane];
    }
    unsigned ew = vo ^ va;                       // edge: window not uniform
    unsigned tc = s_tw[warp + RAD][lane];        // center target bits

    const int y = y0 + warp;
    const float* xbase = x + (size_t)b * 2 * HGT * WID;
    const float4* x0r = (const float4*)(xbase + (size_t)y * WID);
    const float4* x1r = (const float4*)(xbase + (size_t)(HGT + y) * WID);

    float acc = 0.0f;
    #pragma unroll
    for (int k = 0; k < 8; k++) {
        // lane processes cols [4*lane + 128*k, +4): coalesced 512B float4 loads
        int src = 4 * k + (lane >> 3);           // lane holding the bit word
        unsigned ewk = __shfl_sync(0xffffffffu, ew, src);
        unsigned twk = __shfl_sync(0xffffffffu, tc, src);
        int bitbase = (lane & 7) * 4;
        int idx4 = lane + 32 * k;
        float4 a0 = x0r[idx4];
        float4 a1 = x1r[idx4];
        #pragma unroll
        for (int j = 0; j < 4; j++) {
            float v0 = (&a0.x)[j];
            float v1 = (&a1.x)[j];
            unsigned tb = (twk >> (bitbase + j)) & 1u;
            unsigned eb = (ewk >> (bitbase + j)) & 1u;
            float xt = tb ? v1 : v0;
            float xo = tb ? v0 : v1;
            float mx  = fmaxf(v0, v1);
            float lse = mx + __logf(1.0f + __expf(-fabsf(v0 - v1)));
            float c_off = xt - lse;
            float c_on  = 0.95f * xt + 0.1f * xo - 1.05f * lse;
            acc += eb ? c_on : c_off;
        }
    }

    // ---- block reduction -> per-block partial ----
    #pragma unroll
    for (int o = 16; o > 0; o >>= 1)
        acc += __shfl_xor_sync(0xffffffffu, acc, o);

    __shared__ float ws[8];
    if (lane == 0) ws[warp] = acc;
    __syncthreads();

    __shared__ bool amLast;
    if (threadIdx.x == 0) {
        float s = 0.0f;
        #pragma unroll
        for (int i = 0; i < 8; i++) s += ws[i];
        g_part[blockIdx.x] = s;
        __threadfence();
        unsigned v = atomicAdd(&g_done, 1u);
        amLast = (v == NBLK - 1);
    }
    __syncthreads();

    // ---- last block finalizes (deterministic; resets counter for replay) ----
    if (amLast) {
        const int tid = threadIdx.x;
        double s = 0.0;
        #pragma unroll
        for (int i = 0; i < NBLK / 256; i++)
            s += (double)((volatile float*)g_part)[tid + 256 * i];
        #pragma unroll
        for (int o = 16; o > 0; o >>= 1)
            s += __shfl_xor_sync(0xffffffffu, s, o);
        __shared__ double wd[8];
        if (lane == 0) wd[warp] = s;
        __syncthreads();
        if (tid == 0) {
            double t = 0.0;
            #pragma unroll
            for (int i = 0; i < 8; i++) t += wd[i];
            out[0] = (float)(-t / NPIX);
            g_done = 0;                          // reset for next graph replay
        }
    }
}

extern "C" void kernel_launch(void* const* d_in, const int* in_sizes, int n_in,
                              void* d_out, int out_size)
{
    (void)in_sizes; (void)n_in; (void)out_size;
    const float* x   = (const float*)d_in[0];   // [8,2,1024,1024] float32
    const int*   tgt = (const int*)d_in[1];     // [8,1,1024,1024] int32

    edge_loss_kernel<<<NBLK, 256>>>(x, tgt, (float*)d_out);
}

// round 11
// speedup vs baseline: 1.3771x; 1.0270x over previous
#include <cuda_runtime.h>
#include <cstdint>

#define HGT   1024
#define WID   1024
#define TY    8                      // output rows per block
#define RAD   5                      // 11x11 window radius
#define NROWS (TY + 2 * RAD)         // 18 halo rows per block
#define NBLK  1024                   // 8 images * 128 slabs
#define NPIX  (8.0 * 1024.0 * 1024.0)

__device__ float    g_part[NBLK];
__device__ unsigned g_done = 0;

__global__ __launch_bounds__(256, 4)
void edge_loss_kernel(const float* __restrict__ x, const int* __restrict__ tgt,
                      float* __restrict__ out)
{
    const int lane = threadIdx.x & 31;
    const int warp = threadIdx.x >> 5;
    const int b    = blockIdx.x >> 7;            // image
    const int y0   = (blockIdx.x & 127) * TY;    // first output row of slab

    __shared__ uint2    s_ha[NROWS][32];         // .x = horiz OR, .y = horiz AND
    __shared__ unsigned s_tw[NROWS][32];

    const int y = y0 + warp;                     // this warp's output row
    const float* xbase = x + (size_t)b * 2 * HGT * WID;
    const float4* x0r = (const float4*)(xbase + (size_t)y * WID);
    const float4* x1r = (const float4*)(xbase + (size_t)(HGT + y) * WID);

    // ---- Prefetch x batches 0,1 (k=0..3, both channels) before Phase A ----
    float4 p0[2][2], p1[2][2];                   // [buf][pair-half]
    #pragma unroll
    for (int h = 0; h < 2; h++) {
        p0[0][h] = x0r[lane + 32 * (0 + h)];
        p1[0][h] = x1r[lane + 32 * (0 + h)];
        p0[1][h] = x0r[lane + 32 * (2 + h)];
        p1[1][h] = x1r[lane + 32 * (2 + h)];
    }

    // ---- Phase A (cooperative): pack 18 halo rows, horizontal OR/AND +-5 ----
    const int* tbase = tgt + (size_t)b * HGT * WID;
    for (int i = warp; i < NROWS; i += 8) {
        int row = y0 - RAD + i;
        unsigned w = 0u;
        if (row >= 0 && row < HGT) {
            const uint4* p = (const uint4*)(tbase + (size_t)row * WID + lane * 32);
            #pragma unroll
            for (int q = 0; q < 8; q++) {
                uint4 u = p[q];                  // target values are 0 or 1
                unsigned nib = u.x | (u.y << 1) | (u.z << 2) | (u.w << 3);
                w |= nib << (4 * q);
            }
        }
        unsigned wl = __shfl_up_sync(0xffffffffu, w, 1);
        unsigned wr = __shfl_down_sync(0xffffffffu, w, 1);
        if (lane == 0)  wl = 0u;                 // zero padding left
        if (lane == 31) wr = 0u;                 // zero padding right
        unsigned o = w, a = w;
        #pragma unroll
        for (int s = 1; s <= RAD; s++) {
            unsigned r = __funnelshift_r(w, wr, s);
            unsigned l = __funnelshift_l(wl, w, s);
            o |= r | l;
            a &= r & l;
        }
        s_tw[i][lane] = w;
        s_ha[i][lane] = make_uint2(o, a);
    }
    __syncthreads();

    // ---- Vertical combine from smem (uint2 => half the LDS count) ----
    uint2 h0 = s_ha[warp][lane];
    unsigned vo = h0.x, va = h0.y;
    #pragma unroll
    for (int d = 1; d <= 2 * RAD; d++) {
        uint2 hh = s_ha[warp + d][lane];
        vo |= hh.x;
        va &= hh.y;
    }
    unsigned ew = vo ^ va;                       // edge: window not uniform
    unsigned tc = s_tw[warp + RAD][lane];        // center target bits

    // ---- Assemble per-lane bit words: bit 4k+j = col 128k + 4*lane + j ----
    unsigned ebits = 0u, tbits = 0u;
    const int src0 = lane >> 3, sh = 4 * (lane & 7);
    #pragma unroll
    for (int k = 0; k < 8; k++) {
        unsigned e = __shfl_sync(0xffffffffu, ew, 4 * k + src0);
        unsigned t = __shfl_sync(0xffffffffu, tc, 4 * k + src0);
        ebits |= ((e >> sh) & 0xFu) << (4 * k);
        tbits |= ((t >> sh) & 0xFu) << (4 * k);
    }

    // ---- Phase B: software-pipelined loss over 4 k-pair batches ----
    float acc = 0.0f;
    #pragma unroll
    for (int kb = 0; kb < 4; kb++) {
        const int cur = kb & 1;
        float4 v0a = p0[cur][0], v0b = p0[cur][1];
        float4 v1a = p1[cur][0], v1b = p1[cur][1];
        if (kb < 2) {                            // refill: batch kb+2
            #pragma unroll
            for (int h = 0; h < 2; h++) {
                p0[cur][h] = x0r[lane + 32 * (2 * (kb + 2) + h)];
                p1[cur][h] = x1r[lane + 32 * (2 * (kb + 2) + h)];
            }
        }
        #pragma unroll
        for (int h = 0; h < 2; h++) {
            float4 c0 = h ? v0b : v0a;
            float4 c1 = h ? v1b : v1a;
            const int base = 4 * (2 * kb + h);
            #pragma unroll
            for (int j = 0; j < 4; j++) {
                float v0 = (&c0.x)[j];
                float v1 = (&c1.x)[j];
                unsigned tb = (tbits >> (base + j)) & 1u;
                unsigned eb = (ebits >> (base + j)) & 1u;
                float xt = tb ? v1 : v0;
                float xo = tb ? v0 : v1;
                float mx  = fmaxf(v0, v1);
                float lse = mx + __logf(1.0f + __expf(-fabsf(v0 - v1)));
                float c_off = xt - lse;
                float c_on  = 0.95f * xt + 0.1f * xo - 1.05f * lse;
                acc += eb ? c_on : c_off;
            }
        }
    }

    // ---- block reduction -> per-block partial ----
    #pragma unroll
    for (int o = 16; o > 0; o >>= 1)
        acc += __shfl_xor_sync(0xffffffffu, acc, o);

    __shared__ float ws[8];
    if (lane == 0) ws[warp] = acc;
    __syncthreads();

    __shared__ bool amLast;
    if (threadIdx.x == 0) {
        float s = 0.0f;
        #pragma unroll
        for (int i = 0; i < 8; i++) s += ws[i];
        g_part[blockIdx.x] = s;
        __threadfence();
        unsigned v = atomicAdd(&g_done, 1u);
        amLast = (v == NBLK - 1);
    }
    __syncthreads();

    // ---- last block finalizes (deterministic; resets counter for replay) ----
    if (amLast) {
        const int tid = threadIdx.x;
        double s = 0.0;
        #pragma unroll
        for (int i = 0; i < NBLK / 256; i++)
            s += (double)((volatile float*)g_part)[tid + 256 * i];
        #pragma unroll
        for (int o = 16; o > 0; o >>= 1)
            s += __shfl_xor_sync(0xffffffffu, s, o);
        __shared__ double wd[8];
        if (lane == 0) wd[warp] = s;
        __syncthreads();
        if (tid == 0) {
            double t = 0.0;
            #pragma unroll
            for (int i = 0; i < 8; i++) t += wd[i];
            out[0] = (float)(-t / NPIX);
            g_done = 0;                          // reset for next graph replay
        }
    }
}

extern "C" void kernel_launch(void* const* d_in, const int* in_sizes, int n_in,
                              void* d_out, int out_size)
{
    (void)in_sizes; (void)n_in; (void)out_size;
    const float* x   = (const float*)d_in[0];   // [8,2,1024,1024] float32
    const int*   tgt = (const int*)d_in[1];     // [8,1,1024,1024] int32

    edge_loss_kernel<<<NBLK, 256>>>(x, tgt, (float*)d_out);
}

// round 12
// speedup vs baseline: 1.5374x; 1.1164x over previous
#include <cuda_runtime.h>
#include <cstdint>

#define HGT   1024
#define WID   1024
#define TY    16                     // output rows per block (2 per warp)
#define RAD   5                      // 11x11 window radius
#define NROWS (TY + 2 * RAD)         // 26 halo rows per block
#define NBLK  512                    // 8 images * 64 slabs -> single wave
#define NPIX  (8.0 * 1024.0 * 1024.0)

__device__ float    g_part[NBLK];
__device__ unsigned g_done = 0;

__global__ __launch_bounds__(256, 4)
void edge_loss_kernel(const float* __restrict__ x, const int* __restrict__ tgt,
                      float* __restrict__ out)
{
    const int lane = threadIdx.x & 31;
    const int warp = threadIdx.x >> 5;
    const int b    = blockIdx.x >> 6;            // image
    const int y0   = (blockIdx.x & 63) * TY;     // first output row of slab

    __shared__ uint2    s_ha[NROWS][32];         // .x = horiz OR, .y = horiz AND
    __shared__ unsigned s_tw[NROWS][32];

    // ---- Phase A (cooperative): pack 26 halo rows, horizontal OR/AND +-5 ----
    const int* tbase = tgt + (size_t)b * HGT * WID;
    for (int i = warp; i < NROWS; i += 8) {
        int row = y0 - RAD + i;
        unsigned w = 0u;
        if (row >= 0 && row < HGT) {
            const uint4* p = (const uint4*)(tbase + (size_t)row * WID + lane * 32);
            #pragma unroll
            for (int q = 0; q < 8; q++) {
                uint4 u = p[q];                  // target values are 0 or 1
                unsigned nib = u.x | (u.y << 1) | (u.z << 2) | (u.w << 3);
                w |= nib << (4 * q);
            }
        }
        unsigned wl = __shfl_up_sync(0xffffffffu, w, 1);
        unsigned wr = __shfl_down_sync(0xffffffffu, w, 1);
        if (lane == 0)  wl = 0u;                 // zero padding left
        if (lane == 31) wr = 0u;                 // zero padding right
        unsigned o = w, a = w;
        #pragma unroll
        for (int s = 1; s <= RAD; s++) {
            unsigned r = __funnelshift_r(w, wr, s);
            unsigned l = __funnelshift_l(wl, w, s);
            o |= r | l;
            a &= r & l;
        }
        s_tw[i][lane] = w;
        s_ha[i][lane] = make_uint2(o, a);
    }
    __syncthreads();

    // ---- Vertical combine: rows t0=2*warp, t0+1 share 10 of 11 halo rows ----
    const int t0 = 2 * warp;
    unsigned co = 0u, ca = 0xffffffffu;          // common: halo rows t0+1..t0+10
    #pragma unroll
    for (int d = 1; d <= 10; d++) {
        uint2 hh = s_ha[t0 + d][lane];
        co |= hh.x;
        ca &= hh.y;
    }
    uint2 hA = s_ha[t0][lane];
    uint2 hB = s_ha[t0 + 11][lane];
    unsigned ew0 = (co | hA.x) ^ (ca & hA.y);    // edge bits, row 0
    unsigned ew1 = (co | hB.x) ^ (ca & hB.y);    // edge bits, row 1
    unsigned tc0 = s_tw[t0 + RAD][lane];
    unsigned tc1 = s_tw[t0 + RAD + 1][lane];

    // ---- Assemble per-lane bit words: bit 4k+j = col 128k + 4*lane + j ----
    unsigned eb[2] = {0u, 0u}, tb[2] = {0u, 0u};
    const int src0 = lane >> 3, sh = 4 * (lane & 7);
    #pragma unroll
    for (int k = 0; k < 8; k++) {
        unsigned e0 = __shfl_sync(0xffffffffu, ew0, 4 * k + src0);
        unsigned t0s = __shfl_sync(0xffffffffu, tc0, 4 * k + src0);
        unsigned e1 = __shfl_sync(0xffffffffu, ew1, 4 * k + src0);
        unsigned t1s = __shfl_sync(0xffffffffu, tc1, 4 * k + src0);
        eb[0] |= ((e0 >> sh) & 0xFu) << (4 * k);
        tb[0] |= ((t0s >> sh) & 0xFu) << (4 * k);
        eb[1] |= ((e1 >> sh) & 0xFu) << (4 * k);
        tb[1] |= ((t1s >> sh) & 0xFu) << (4 * k);
    }

    // ---- Phase B: flat 16-iter loop (2 rows x 8 k), depth-2 prefetch ----
    const int yA = y0 + t0;
    const float* xbase = x + (size_t)b * 2 * HGT * WID;
    const float4* x0r[2] = { (const float4*)(xbase + (size_t)yA * WID),
                             (const float4*)(xbase + (size_t)(yA + 1) * WID) };
    const float4* x1r[2] = { (const float4*)(xbase + (size_t)(HGT + yA) * WID),
                             (const float4*)(xbase + (size_t)(HGT + yA + 1) * WID) };

    float4 b0[2], b1[2];                         // rolling 2-deep buffers
    b0[0] = __ldcs(&x0r[0][lane]);
    b1[0] = __ldcs(&x1r[0][lane]);
    b0[1] = __ldcs(&x0r[0][lane + 32]);
    b1[1] = __ldcs(&x1r[0][lane + 32]);

    float acc = 0.0f;
    #pragma unroll
    for (int m = 0; m < 16; m++) {
        const int cur = m & 1;
        float4 v0 = b0[cur];
        float4 v1 = b1[cur];
        if (m < 14) {                            // prefetch iteration m+2
            const int mn = m + 2;
            const int rn = mn >> 3, kn = mn & 7;
            b0[cur] = __ldcs(&x0r[rn][lane + 32 * kn]);
            b1[cur] = __ldcs(&x1r[rn][lane + 32 * kn]);
        }
        const int r = m >> 3, base = 4 * (m & 7);
        const unsigned ebw = eb[r], tbw = tb[r];
        #pragma unroll
        for (int j = 0; j < 4; j++) {
            float a0 = (&v0.x)[j];
            float a1 = (&v1.x)[j];
            unsigned tbit = (tbw >> (base + j)) & 1u;
            unsigned ebit = (ebw >> (base + j)) & 1u;
            float xt = tbit ? a1 : a0;
            float xo = tbit ? a0 : a1;
            float mx  = fmaxf(a0, a1);
            float lse = mx + __logf(1.0f + __expf(-fabsf(a0 - a1)));
            float c_off = xt - lse;
            float c_on  = 0.95f * xt + 0.1f * xo - 1.05f * lse;
            acc += ebit ? c_on : c_off;
        }
    }

    // ---- block reduction -> per-block partial ----
    #pragma unroll
    for (int o = 16; o > 0; o >>= 1)
        acc += __shfl_xor_sync(0xffffffffu, acc, o);

    __shared__ float ws[8];
    if (lane == 0) ws[warp] = acc;
    __syncthreads();

    __shared__ bool amLast;
    if (threadIdx.x == 0) {
        float s = 0.0f;
        #pragma unroll
        for (int i = 0; i < 8; i++) s += ws[i];
        g_part[blockIdx.x] = s;
        __threadfence();
        unsigned v = atomicAdd(&g_done, 1u);
        amLast = (v == NBLK - 1);
    }
    __syncthreads();

    // ---- last block finalizes (deterministic; resets counter for replay) ----
    if (amLast) {
        const int tid = threadIdx.x;
        double s = 0.0;
        #pragma unroll
        for (int i = 0; i < NBLK / 256; i++)
            s += (double)((volatile float*)g_part)[tid + 256 * i];
        #pragma unroll
        for (int o = 16; o > 0; o >>= 1)
            s += __shfl_xor_sync(0xffffffffu, s, o);
        __shared__ double wd[8];
        if (lane == 0) wd[warp] = s;
        __syncthreads();
        if (tid == 0) {
            double t = 0.0;
            #pragma unroll
            for (int i = 0; i < 8; i++) t += wd[i];
            out[0] = (float)(-t / NPIX);
            g_done = 0;                          // reset for next graph replay
        }
    }
}

extern "C" void kernel_launch(void* const* d_in, const int* in_sizes, int n_in,
                              void* d_out, int out_size)
{
    (void)in_sizes; (void)n_in; (void)out_size;
    const float* x   = (const float*)d_in[0];   // [8,2,1024,1024] float32
    const int*   tgt = (const int*)d_in[1];     // [8,1,1024,1024] int32

    edge_loss_kernel<<<NBLK, 256>>>(x, tgt, (float*)d_out);
}